// round 9
// baseline (speedup 1.0000x reference)
#include <cuda_runtime.h>
#include <cuda.h>
#include <cuda_fp16.h>
#include <cstdint>
#include <cstddef>

// ============================================================================
// Device scratch (allocation-free rule: static __device__ globals)
// ============================================================================
static __device__ __align__(1024) __half g_Xh[8192ull * 4096ull];   // 64 MB
static __device__ __align__(1024) __half g_Wh[4096ull * 4096ull];   // 32 MB

// ============================================================================
// Baseline-PTX helpers (harness assembles for sm_103 WITHOUT 'a' ->
// no tcgen05/TMEM/cg2). Everything here is sm_80-era PTX:
// cp.async, ldmatrix, mma.sync.
// ============================================================================
__device__ __forceinline__ uint32_t smem_u32(const void* p) {
    uint32_t a;
    asm("{ .reg .u64 t; cvta.to.shared.u64 t, %1; cvt.u32.u64 %0, t; }"
        : "=r"(a) : "l"(p));
    return a;
}

#define CP_ASYNC16(dst, src) \
    asm volatile("cp.async.cg.shared.global [%0], [%1], 16;" \
        :: "r"(dst), "l"(src) : "memory")

#define CP_COMMIT() asm volatile("cp.async.commit_group;" ::: "memory")

#define CP_WAIT1() asm volatile("cp.async.wait_group 1;" ::: "memory")

#define LDSM_X4(r0, r1, r2, r3, addr) \
    asm volatile("ldmatrix.sync.aligned.m8n8.x4.shared.b16 {%0,%1,%2,%3}, [%4];" \
        : "=r"(r0), "=r"(r1), "=r"(r2), "=r"(r3) : "r"(addr))

#define MMA16816(c0, c1, c2, c3, a0, a1, a2, a3, b0, b1)                        \
    asm volatile(                                                               \
        "mma.sync.aligned.m16n8k16.row.col.f32.f16.f16.f32 "                    \
        "{%0,%1,%2,%3}, {%4,%5,%6,%7}, {%8,%9}, {%0,%1,%2,%3};"                 \
        : "+f"(c0), "+f"(c1), "+f"(c2), "+f"(c3)                                \
        : "r"(a0), "r"(a1), "r"(a2), "r"(a3), "r"(b0), "r"(b1))

// ============================================================================
// Kernel 1: NVFP4 quantize->dequantize (fp32 in, fp16 out), 32-elem blocks.
// One warp-iter = 128 consecutive floats via LDG.128 (float4/lane); a 32-elem
// quant block spans exactly 8 lanes, amax reduce = 3 local fmax + 3 shfl_xor
// (offsets 4/2/1 stay inside the 8-lane segment). Output packs 4 halves ->
// uint2 (STG.64). IEEE RN divisions -> bit-identical to the JAX reference.
// ============================================================================
__global__ void __launch_bounds__(256) nvfp4_qdq_kernel(
    const float4* __restrict__ in4, uint2* __restrict__ out2, int nchunks)
{
    const int lane = threadIdx.x & 31;
    const int warp = blockIdx.x * (blockDim.x >> 5) + (threadIdx.x >> 5);
    const int nwarps = gridDim.x * (blockDim.x >> 5);

    for (int c = warp; c < nchunks; c += nwarps) {           // chunk = 128 floats
        const float4 v = in4[(size_t)c * 32 + lane];
        float a = fmaxf(fmaxf(fabsf(v.x), fabsf(v.y)),
                        fmaxf(fabsf(v.z), fabsf(v.w)));
        a = fmaxf(a, __shfl_xor_sync(0xFFFFFFFFu, a, 4));
        a = fmaxf(a, __shfl_xor_sync(0xFFFFFFFFu, a, 2));
        a = fmaxf(a, __shfl_xor_sync(0xFFFFFFFFu, a, 1));
        const float s1 = __fdiv_rn(fmaxf(a, 1e-12f), 6.0f);  // dequant scale
        const float dv = fmaxf(s1, 1e-12f);                  // divisor (ref quirk)

        const float xv[4] = {v.x, v.y, v.z, v.w};
        uint16_t h[4];
        #pragma unroll
        for (int u = 0; u < 4; ++u) {
            float xs = __fdiv_rn(xv[u], dv);                 // IEEE RN = JAX
            xs = fminf(fmaxf(xs, -6.0f), 6.0f);
            const float sgn = (xs >= 0.0f) ? 1.0f : -1.0f;
            const float aa = fabsf(xs);
            const float qa =
                aa < 0.25f ? 0.0f :
                aa < 0.75f ? 0.5f :
                aa < 1.25f ? 1.0f :
                aa < 1.75f ? 1.5f :
                aa < 2.5f  ? 2.0f :
                aa < 3.5f  ? 3.0f :
                aa < 5.0f  ? 4.0f : 6.0f;
            h[u] = __half_as_ushort(__float2half_rn(sgn * qa * s1));
        }
        uint2 o;
        o.x = (uint32_t)h[0] | ((uint32_t)h[1] << 16);
        o.y = (uint32_t)h[2] | ((uint32_t)h[3] << 16);
        out2[(size_t)c * 32 + lane] = o;
    }
}

// ============================================================================
// Kernel 2: fp16 GEMM via mma.sync.m16n8k16 (baseline PTX; no tcgen05).
//   D[M,N] = Xh[M,K] * Wh[N,K]^T, fp32 out.
// CTA tile 128x128, 256 threads = 8 warps (4 m x 2 n), warp tile 32x64.
// K-chunk 64 (128B rows, 8-row XOR swizzle), 3-stage cp.async pipeline
// (96 KB dynamic smem). __launch_bounds__(256,2) caps regs at 128 so
// 2 CTAs/SM co-reside (192 KB smem <= 228 KB): the peer CTA's MMAs hide
// this CTA's per-iteration barrier + wait_group bubbles.
// A row-major, B "col" = [N,K] K-contiguous = exact .row.col mma layout.
// ============================================================================
static constexpr int TM = 128;
static constexpr int TN = 128;
static constexpr int KC = 64;                       // K elems per stage
static constexpr int STAGES = 3;
static constexpr int AT_BYTES = TM * KC * 2;        // 16384
static constexpr int STG_BYTES = 2 * AT_BYTES;      // 32768 (A then B)
static constexpr int SMEM_NEEDED = STAGES * STG_BYTES;  // 98304

__global__ void __launch_bounds__(256, 2) nvfp4_gemm_hmma_kernel(
    float* __restrict__ out,
    const __half* __restrict__ A,   // [M,K]
    const __half* __restrict__ B,   // [N,K]
    int M, int N, int K)
{
    extern __shared__ char dyn_smem[];
    const uint32_t sbase = smem_u32(dyn_smem);

    const int tid  = threadIdx.x;
    const int lane = tid & 31;
    const int wid  = tid >> 5;
    const int wm   = wid & 3;          // 4 warps along M (32 rows each)
    const int wn   = wid >> 2;         // 2 warps along N (64 cols each)
    const int m0   = blockIdx.x * TM;
    const int n0   = blockIdx.y * TN;
    const int kiters = K / KC;         // 64
    const size_t rowK2 = (size_t)K * 2;  // gmem row stride in bytes

    // ---- loader thread constants: thread t covers (row = t>>3 + 32p, chunk = t&7)
    const int ldRow0 = tid >> 3;
    const int ldC16  = (tid & 7) * 16;                 // byte offset along K
    const char* gA = (const char*)A + (size_t)(m0 + ldRow0) * rowK2 + ldC16;
    const char* gB = (const char*)B + (size_t)(n0 + ldRow0) * rowK2 + ldC16;

    // smem store offsets (swizzled); row's XOR value = (row&7)<<4
    uint32_t stOff[4];
    #pragma unroll
    for (int p = 0; p < 4; ++p) {
        const int r = ldRow0 + 32 * p;
        stOff[p] = (uint32_t)(r * 128 + (ldC16 ^ ((r & 7) << 4)));
    }

    // ---- ldmatrix address constants
    // x4: lanes 0-7/8-15/16-23/24-31 supply row addrs of mats 0-3.
    // fRow/kSel gives mats {rows0-7 k0-7, rows8-15 k0-7, rows0-7 k8-15,
    // rows8-15 k8-15} = exactly the a0..a3 / {b0-pair} orders mma wants.
    const int fRow = lane & 15;
    const uint32_t kSel = (uint32_t)((lane >> 4) * 16);   // byte
    uint32_t aOff[2], aXor[2];
    #pragma unroll
    for (int mt = 0; mt < 2; ++mt) {
        const int r = wm * 32 + mt * 16 + fRow;
        aOff[mt] = (uint32_t)(r * 128);
        aXor[mt] = (uint32_t)((r & 7) << 4);
    }
    uint32_t bOff[4], bXor[4];
    #pragma unroll
    for (int np = 0; np < 4; ++np) {
        const int r = wn * 64 + np * 16 + fRow;
        bOff[np] = (uint32_t)(r * 128);
        bXor[np] = (uint32_t)((r & 7) << 4);
    }

    float acc[2][8][4];
    #pragma unroll
    for (int mt = 0; mt < 2; ++mt)
        #pragma unroll
        for (int nt = 0; nt < 8; ++nt)
            #pragma unroll
            for (int q = 0; q < 4; ++q) acc[mt][nt][q] = 0.0f;

    // ---- prologue: fill stages 0,1
    #pragma unroll
    for (int s = 0; s < 2; ++s) {
        const uint32_t sb = sbase + s * STG_BYTES;
        #pragma unroll
        for (int p = 0; p < 4; ++p) {
            CP_ASYNC16(sb + stOff[p],            gA + (size_t)(s * 128) + (size_t)(32 * p) * rowK2);
            CP_ASYNC16(sb + AT_BYTES + stOff[p], gB + (size_t)(s * 128) + (size_t)(32 * p) * rowK2);
        }
        CP_COMMIT();
    }

    // ---- mainloop
    for (int it = 0; it < kiters; ++it) {
        CP_WAIT1();              // pending={it,it+1} -> stage `it` landed
        __syncthreads();         // visibility + stage it-1 slot fully drained

        const int nx = it + 2;
        if (nx < kiters) {
            const uint32_t sb = sbase + (nx % STAGES) * STG_BYTES;
            const size_t kB = (size_t)nx * 128;
            #pragma unroll
            for (int p = 0; p < 4; ++p) {
                CP_ASYNC16(sb + stOff[p],            gA + kB + (size_t)(32 * p) * rowK2);
                CP_ASYNC16(sb + AT_BYTES + stOff[p], gB + kB + (size_t)(32 * p) * rowK2);
            }
        }
        CP_COMMIT();             // empty group near tail keeps wait counts aligned

        const uint32_t as = sbase + (it % STAGES) * STG_BYTES;
        const uint32_t bs = as + AT_BYTES;
        #pragma unroll
        for (int ks = 0; ks < 4; ++ks) {
            const uint32_t kb = (uint32_t)(ks * 32) + kSel;
            uint32_t a[2][4];
            #pragma unroll
            for (int mt = 0; mt < 2; ++mt) {
                // mats: {m0-7 k0-7, m8-15 k0-7, m0-7 k8-15, m8-15 k8-15} = a0..a3
                LDSM_X4(a[mt][0], a[mt][1], a[mt][2], a[mt][3],
                        as + aOff[mt] + (kb ^ aXor[mt]));
            }
            #pragma unroll
            for (int np = 0; np < 4; ++np) {
                // mats: {n0-7 k0-7, n8-15 k0-7, n0-7 k8-15, n8-15 k8-15}
                // -> n-tile 2np: {q0,q2}, n-tile 2np+1: {q1,q3}
                uint32_t q0, q1, q2, q3;
                LDSM_X4(q0, q1, q2, q3, bs + bOff[np] + (kb ^ bXor[np]));
                #pragma unroll
                for (int mt = 0; mt < 2; ++mt) {
                    MMA16816(acc[mt][2*np][0],   acc[mt][2*np][1],
                             acc[mt][2*np][2],   acc[mt][2*np][3],
                             a[mt][0], a[mt][1], a[mt][2], a[mt][3], q0, q2);
                    MMA16816(acc[mt][2*np+1][0], acc[mt][2*np+1][1],
                             acc[mt][2*np+1][2], acc[mt][2*np+1][3],
                             a[mt][0], a[mt][1], a[mt][2], a[mt][3], q1, q3);
                }
            }
        }
    }

    // ---- epilogue: c-frag lane map: (m = lane>>2 [+8], n = (lane&3)*2)
    const int erow = m0 + wm * 32 + (lane >> 2);
    const int ecol = n0 + wn * 64 + (lane & 3) * 2;
    #pragma unroll
    for (int mt = 0; mt < 2; ++mt) {
        #pragma unroll
        for (int nt = 0; nt < 8; ++nt) {
            float* p0 = out + (size_t)(erow + mt * 16)     * N + ecol + nt * 8;
            float* p1 = out + (size_t)(erow + mt * 16 + 8) * N + ecol + nt * 8;
            *reinterpret_cast<float2*>(p0) = make_float2(acc[mt][nt][0], acc[mt][nt][1]);
            *reinterpret_cast<float2*>(p1) = make_float2(acc[mt][nt][2], acc[mt][nt][3]);
        }
    }
}

// ============================================================================
// Host: kernel_launch (graph-capturable, allocation-free)
// ============================================================================
extern "C" void kernel_launch(void* const* d_in, const int* in_sizes, int n_in,
                              void* d_out, int out_size)
{
    const float* x = (const float*)d_in[0];
    const float* w = (const float*)d_in[1];
    const int K = 4096;
    const int M = in_sizes[0] / K;   // 8192
    const int N = in_sizes[1] / K;   // 4096

    __half* Xh = nullptr;
    __half* Wh = nullptr;
    cudaGetSymbolAddress((void**)&Xh, g_Xh);
    cudaGetSymbolAddress((void**)&Wh, g_Wh);

    // 1+2: quantize->dequantize to fp16 (vectorized: 128 floats per warp-iter)
    nvfp4_qdq_kernel<<<2048, 256>>>((const float4*)x, (uint2*)Xh, M * K / 128);
    nvfp4_qdq_kernel<<<1024, 256>>>((const float4*)w, (uint2*)Wh, N * K / 128);

    // 3: fp16 mma.sync GEMM
    cudaFuncSetAttribute(nvfp4_gemm_hmma_kernel,
                         cudaFuncAttributeMaxDynamicSharedMemorySize, SMEM_NEEDED);
    dim3 grid(M / TM, N / TN);   // (64, 32)
    nvfp4_gemm_hmma_kernel<<<grid, 256, SMEM_NEEDED>>>(
        (float*)d_out, Xh, Wh, M, N, K);
}